// round 1
// baseline (speedup 1.0000x reference)
#include <cuda_runtime.h>
#include <math.h>

// Q_MultiHeadedAttention: analytically collapsed quantum attention.
// SEQ=4, D=8, NQ=3, DIM=8. Output [4,3] float32 (12 elems).
//
// Derivation (see analysis): all density matrices are rank-1 pure states;
// CNOT perms + partial traces reduce to per-qubit Z expectations:
//   phi_i = (pi/6) * ( S_k0 * sum_t Zq_i[t]  +  sum_t Zq_i[t]*Zk0[t] )
//   out[i,t] = ( Sv1*Sv2*Sv3 * Z_t( |u(phi_i)^x3 psi_v0|^2 ) + 1 ) / 2
// where psi = U x, x = |row| / (||row|| + 1e-12), U = kron of per-qubit
// Rz(w2)Ry(w1)Rx(w0) with w scaled by W_MUL = sqrt(2/5).

#define W_MUL 0.6324555320336759f
#define PI_F  3.14159265358979323846f

struct c2x2 { float2 m[2][2]; };

__device__ __forceinline__ float2 cmul(float2 a, float2 b) {
    return make_float2(a.x * b.x - a.y * b.y, a.x * b.y + a.y * b.x);
}
__device__ __forceinline__ float2 cadd(float2 a, float2 b) {
    return make_float2(a.x + b.x, a.y + b.y);
}

// u = Rz(wz) @ Ry(wy) @ Rx(wx)
__device__ void make_u(float wx, float wy, float wz, c2x2& u) {
    float c0, s0, c1, s1, c2, s2;
    sincosf(wx * 0.5f, &s0, &c0);
    sincosf(wy * 0.5f, &s1, &c1);
    sincosf(wz * 0.5f, &s2, &c2);
    // M = Ry @ Rx
    float2 M00 = make_float2( c1 * c0,  s1 * s0);
    float2 M01 = make_float2(-s1 * c0, -c1 * s0);
    float2 M10 = make_float2( s1 * c0, -c1 * s0);
    float2 M11 = make_float2( c1 * c0, -s1 * s0);
    float2 e0 = make_float2(c2, -s2);   // exp(-i wz/2)
    float2 e1 = make_float2(c2,  s2);   // exp(+i wz/2)
    u.m[0][0] = cmul(e0, M00); u.m[0][1] = cmul(e0, M01);
    u.m[1][0] = cmul(e1, M10); u.m[1][1] = cmul(e1, M11);
}

// apply single-qubit gate u on qubit q (q=0 is MSB) of 8-dim state
__device__ void apply_gate(float2 psi[8], const c2x2& u, int q) {
    int stride = 1 << (2 - q);
    #pragma unroll
    for (int a = 0; a < 8; a++) {
        if (a & stride) continue;
        float2 v0 = psi[a], v1 = psi[a + stride];
        psi[a]          = cadd(cmul(u.m[0][0], v0), cmul(u.m[0][1], v1));
        psi[a + stride] = cadd(cmul(u.m[1][0], v0), cmul(u.m[1][1], v1));
    }
}

// encoding + unitary: psi = (U0 kron U1 kron U2) * (|row| / (||row||+1e-12))
__device__ void encode_apply(const float* row, const c2x2 U[3], float2 psi[8]) {
    float x[8], n2 = 0.f;
    #pragma unroll
    for (int i = 0; i < 8; i++) { x[i] = fabsf(row[i]); n2 += x[i] * x[i]; }
    float inv = 1.f / (sqrtf(n2) + 1e-12f);
    #pragma unroll
    for (int i = 0; i < 8; i++) psi[i] = make_float2(x[i] * inv, 0.f);
    apply_gate(psi, U[0], 0);
    apply_gate(psi, U[1], 1);
    apply_gate(psi, U[2], 2);
}

// per-qubit Z expectations of |psi|^2, and total probability S
__device__ void zvec(const float2 psi[8], float Z[3], float* S) {
    float p[8], s = 0.f;
    #pragma unroll
    for (int a = 0; a < 8; a++) {
        p[a] = psi[a].x * psi[a].x + psi[a].y * psi[a].y;
        s += p[a];
    }
    #pragma unroll
    for (int t = 0; t < 3; t++) {
        float z = 0.f;
        #pragma unroll
        for (int a = 0; a < 8; a++) z += ((a >> (2 - t)) & 1) ? -p[a] : p[a];
        Z[t] = z;
    }
    if (S) *S = s;
}

__global__ void qattn_kernel(const float* __restrict__ q,
                             const float* __restrict__ k,
                             const float* __restrict__ v,
                             const float* __restrict__ wq,
                             const float* __restrict__ wk,
                             const float* __restrict__ wv,
                             float* __restrict__ out) {
    int i = threadIdx.x;       // output row (query index), 0..3
    if (i >= 4) return;

    c2x2 Uq[3], Uk[3], Uv[3];
    #pragma unroll
    for (int t = 0; t < 3; t++) {
        make_u(wq[3 * t] * W_MUL, wq[3 * t + 1] * W_MUL, wq[3 * t + 2] * W_MUL, Uq[t]);
        make_u(wk[3 * t] * W_MUL, wk[3 * t + 1] * W_MUL, wk[3 * t + 2] * W_MUL, Uk[t]);
        make_u(wv[3 * t] * W_MUL, wv[3 * t + 1] * W_MUL, wv[3 * t + 2] * W_MUL, Uv[t]);
    }

    float2 psi[8], psiv0[8];
    float Zq[3], Zk[3], Sk, dummy;

    // query row i
    encode_apply(q + i * 8, Uq, psi);
    zvec(psi, Zq, &dummy);

    // key row 0 (only row 0 ever matters — register 0 of the output trace)
    encode_apply(k, Uk, psi);
    zvec(psi, Zk, &Sk);

    // value row 0 state (kept), value rows 1..3 only contribute their norms
    encode_apply(v, Uv, psiv0);
    float Sv = 1.f;
    for (int j = 1; j < 4; j++) {
        encode_apply(v + j * 8, Uv, psi);
        float s = 0.f;
        #pragma unroll
        for (int a = 0; a < 8; a++) s += psi[a].x * psi[a].x + psi[a].y * psi[a].y;
        Sv *= s;
    }

    // phi_{i,0} = pi * mean(E) over the 6 QK measurements
    float phi = (PI_F / 6.f) * (Sk * (Zq[0] + Zq[1] + Zq[2])
                                + Zq[0] * Zk[0] + Zq[1] * Zk[1] + Zq[2] * Zk[2]);

    // u(phi) = Rz(phi) Ry(phi/2) Rx(phi/2), applied to all 3 qubits of psi_v0
    c2x2 u;
    make_u(phi * 0.5f, phi * 0.5f, phi, u);
    #pragma unroll
    for (int a = 0; a < 8; a++) psi[a] = psiv0[a];
    apply_gate(psi, u, 0);
    apply_gate(psi, u, 1);
    apply_gate(psi, u, 2);

    float Z0[3];
    zvec(psi, Z0, nullptr);
    #pragma unroll
    for (int t = 0; t < 3; t++)
        out[i * 3 + t] = (Sv * Z0[t] + 1.f) * 0.5f;
}

extern "C" void kernel_launch(void* const* d_in, const int* in_sizes, int n_in,
                              void* d_out, int out_size) {
    const float* q  = (const float*)d_in[0];
    const float* k  = (const float*)d_in[1];
    const float* v  = (const float*)d_in[2];
    const float* wq = (const float*)d_in[3];
    const float* wk = (const float*)d_in[4];
    const float* wv = (const float*)d_in[5];
    float* out = (float*)d_out;
    qattn_kernel<<<1, 4>>>(q, k, v, wq, wk, wv, out);
}

// round 2
// speedup vs baseline: 2.3655x; 2.3655x over previous
#include <cuda_runtime.h>
#include <math.h>

// Q_MultiHeadedAttention: fully analytically collapsed quantum attention.
// SEQ=4, D=8, NQ=3, DIM=8. Output [4,3] float32.
//
// Heisenberg-picture reduction:
//   u = Rz(tz)Ry(ty)Rx(tx)  =>  u^dag Z u = cy*cx*Z + cy*sx*Y - sy*X
//   For real x:   Z_t = cx*cy*d_t - 2*sy*c_t
//     d_t = sum_{bit_t(a)=0} x_a^2 - x_{a+s}^2 ,  c_t = sum x_a*x_{a+s}
//   For psi complex: Z_t = A00*d_t + 2*(ReA01*Re r_t - ImA01*Im r_t),
//     r_t = sum conj(psi_a)*psi_{a+s}
//   Output rotation u(phi): tx=ty=phi/2 => A00=ch^2, ReA01=-sh, ImA01=-ch*sh.
//   Sk = Sv = 1 to fp32 precision (norms preserved; eps=1e-12 invisible).
//   phi_i = (pi/6) * ( sum_t Zq_i[t] + sum_t Zq_i[t]*Zk0[t] )
//   out[i,t] = ( Z_t( u(phi_i)^x3 psi_v0 ) + 1 ) / 2

#define W_MUL 0.6324555320336759f
#define PI_F  3.14159265358979323846f

struct c2x2 { float2 m[2][2]; };

__device__ __forceinline__ float2 cmul(float2 a, float2 b) {
    return make_float2(a.x * b.x - a.y * b.y, a.x * b.y + a.y * b.x);
}
__device__ __forceinline__ float2 cadd(float2 a, float2 b) {
    return make_float2(a.x + b.x, a.y + b.y);
}

// u = Rz(wz) @ Ry(wy) @ Rx(wx), half-angle construction (fast trig)
__device__ __forceinline__ void make_u(float wx, float wy, float wz, c2x2& u) {
    float c0, s0, c1, s1, c2, s2;
    __sincosf(wx * 0.5f, &s0, &c0);
    __sincosf(wy * 0.5f, &s1, &c1);
    __sincosf(wz * 0.5f, &s2, &c2);
    float2 M00 = make_float2( c1 * c0,  s1 * s0);
    float2 M01 = make_float2(-s1 * c0, -c1 * s0);
    float2 M10 = make_float2( s1 * c0, -c1 * s0);
    float2 M11 = make_float2( c1 * c0, -s1 * s0);
    float2 e0 = make_float2(c2, -s2);
    float2 e1 = make_float2(c2,  s2);
    u.m[0][0] = cmul(e0, M00); u.m[0][1] = cmul(e0, M01);
    u.m[1][0] = cmul(e1, M10); u.m[1][1] = cmul(e1, M11);
}

__device__ __forceinline__ void apply_gate(float2 psi[8], const c2x2& u, int q) {
    int stride = 1 << (2 - q);
    #pragma unroll
    for (int a = 0; a < 8; a++) {
        if (a & stride) continue;
        float2 v0 = psi[a], v1 = psi[a + stride];
        psi[a]          = cadd(cmul(u.m[0][0], v0), cmul(u.m[0][1], v1));
        psi[a + stride] = cadd(cmul(u.m[1][0], v0), cmul(u.m[1][1], v1));
    }
}

// d_t, c_t bilinears for a real nonneg vector (already |.|)
__device__ __forceinline__ void dc_real(const float x[8], float d[3], float c[3]) {
    #pragma unroll
    for (int t = 0; t < 3; t++) {
        int s = 1 << (2 - t);
        float dd = 0.f, cc = 0.f;
        #pragma unroll
        for (int a = 0; a < 8; a++) {
            if (a & s) continue;
            dd += x[a] * x[a] - x[a + s] * x[a + s];
            cc += x[a] * x[a + s];
        }
        d[t] = dd; c[t] = cc;
    }
}

// Z_t for real encoded row under circuit with weights w (9 floats)
__device__ __forceinline__ void z_real(const float4 lo, const float4 hi,
                                       const float w[9], float Z[3]) {
    float x[8] = { fabsf(lo.x), fabsf(lo.y), fabsf(lo.z), fabsf(lo.w),
                   fabsf(hi.x), fabsf(hi.y), fabsf(hi.z), fabsf(hi.w) };
    float n2 = 0.f;
    #pragma unroll
    for (int a = 0; a < 8; a++) n2 += x[a] * x[a];
    float inv = __frcp_rn(sqrtf(n2) + 1e-12f);
    float inv2 = inv * inv;
    float d[3], c[3];
    dc_real(x, d, c);
    #pragma unroll
    for (int t = 0; t < 3; t++) {
        float tx = w[3 * t] * W_MUL, ty = w[3 * t + 1] * W_MUL;
        float cx = __cosf(tx);
        float sy, cy;
        __sincosf(ty, &sy, &cy);
        Z[t] = (cx * cy * d[t] - 2.f * sy * c[t]) * inv2;
    }
}

__global__ void qattn_kernel(const float* __restrict__ q,
                             const float* __restrict__ k,
                             const float* __restrict__ v,
                             const float* __restrict__ wq,
                             const float* __restrict__ wk,
                             const float* __restrict__ wv,
                             float* __restrict__ out) {
    int i = threadIdx.x;   // output row, 0..3
    if (i >= 4) return;

    // ---- hoist all global loads (max MLP) ----
    const float4* q4 = (const float4*)(q + i * 8);
    const float4* k4 = (const float4*)k;
    const float4* v4 = (const float4*)v;
    float4 qlo = q4[0], qhi = q4[1];
    float4 klo = k4[0], khi = k4[1];
    float4 vlo = v4[0], vhi = v4[1];
    float wqv[9], wkv[9], wvv[9];
    #pragma unroll
    for (int j = 0; j < 9; j++) { wqv[j] = wq[j]; wkv[j] = wk[j]; wvv[j] = wv[j]; }

    // ---- Zq (row i), Zk (row 0); Sk == 1 to fp32 ----
    float Zq[3], Zk[3];
    z_real(qlo, qhi, wqv, Zq);
    z_real(klo, khi, wkv, Zk);

    float phi = (PI_F / 6.f) * (Zq[0] + Zq[1] + Zq[2]
                                + Zq[0] * Zk[0] + Zq[1] * Zk[1] + Zq[2] * Zk[2]);

    // ---- psi_v0 = Uv * normalized |v0| (the only complex evolution) ----
    float xv[8] = { fabsf(vlo.x), fabsf(vlo.y), fabsf(vlo.z), fabsf(vlo.w),
                    fabsf(vhi.x), fabsf(vhi.y), fabsf(vhi.z), fabsf(vhi.w) };
    float n2 = 0.f;
    #pragma unroll
    for (int a = 0; a < 8; a++) n2 += xv[a] * xv[a];
    float inv = __frcp_rn(sqrtf(n2) + 1e-12f);
    float2 psi[8];
    #pragma unroll
    for (int a = 0; a < 8; a++) psi[a] = make_float2(xv[a] * inv, 0.f);
    c2x2 Uv;
    #pragma unroll
    for (int t = 0; t < 3; t++) {
        make_u(wvv[3 * t] * W_MUL, wvv[3 * t + 1] * W_MUL, wvv[3 * t + 2] * W_MUL, Uv);
        apply_gate(psi, Uv, t);
    }

    // ---- phi-independent bilinears of psi_v0 ----
    float dv[3], rre[3], rim[3];
    #pragma unroll
    for (int t = 0; t < 3; t++) {
        int s = 1 << (2 - t);
        float dd = 0.f, re = 0.f, im = 0.f;
        #pragma unroll
        for (int a = 0; a < 8; a++) {
            if (a & s) continue;
            float2 pa = psi[a], pb = psi[a + s];
            dd += (pa.x * pa.x + pa.y * pa.y) - (pb.x * pb.x + pb.y * pb.y);
            re += pa.x * pb.x + pa.y * pb.y;   // Re(conj(pa)*pb)
            im += pa.x * pb.y - pa.y * pb.x;   // Im(conj(pa)*pb)
        }
        dv[t] = dd; rre[t] = re; rim[t] = im;
    }

    // ---- apply u(phi) observable: A00=ch^2, 2ReA01=-2sh, -2ImA01=+2ch*sh ----
    float sh, ch;
    __sincosf(phi * 0.5f, &sh, &ch);
    float a00 = ch * ch, bre = -2.f * sh, bim = 2.f * ch * sh;
    #pragma unroll
    for (int t = 0; t < 3; t++) {
        float z = a00 * dv[t] + bre * rre[t] + bim * rim[t];
        out[i * 3 + t] = (z + 1.f) * 0.5f;
    }
}

extern "C" void kernel_launch(void* const* d_in, const int* in_sizes, int n_in,
                              void* d_out, int out_size) {
    const float* q  = (const float*)d_in[0];
    const float* k  = (const float*)d_in[1];
    const float* v  = (const float*)d_in[2];
    const float* wq = (const float*)d_in[3];
    const float* wk = (const float*)d_in[4];
    const float* wv = (const float*)d_in[5];
    float* out = (float*)d_out;
    qattn_kernel<<<1, 4>>>(q, k, v, wq, wk, wv, out);
}